// round 8
// baseline (speedup 1.0000x reference)
#include <cuda_runtime.h>
#include <cuda_fp16.h>
#include <cstdint>

// Problem constants (match reference_code)
#define NN 50000
#define EE 800000
#define DD 64

#define TILE 1024
#define NBLK ((NN + TILE - 1) / TILE)   // 49

// ----------------------------------------------------------------------------
// Scratch (device globals; no allocation allowed). BSS-zeroed at load;
// fill_kernel re-zeroes g_deg / g_flag / g_ticket each call, so every graph
// replay sees identical initial state.
// ----------------------------------------------------------------------------
__device__ __half g_h[NN * DD];       // ping (fp16 inter-hop tensor)
__device__ __half g_t[NN * DD];       // pong
__device__ int    g_deg[NN];          // in-degree histogram (zero at entry)
__device__ int    g_rowptr[NN + 1];   // CSR row pointers (by dst)
__device__ int    g_cursor[NN];       // scatter cursors
__device__ volatile int g_bsum[NBLK]; // scan block sums
__device__ volatile int g_flag[NBLK]; // scan lookback flags (zero at entry)
__device__ int    g_ticket[4];        // per-hop work-stealing counters (zero at entry)
__device__ int2   g_csr[EE];          // packed {src, w_bits} per CSR slot

// ----------------------------------------------------------------------------
// 1) init + count fused: g_h = fp16(x); out = 0.25*x; histogram of dst.
// ----------------------------------------------------------------------------
__global__ void init_count_kernel(const float4* __restrict__ x4,
                                  float4* __restrict__ out4,
                                  const int4* __restrict__ dst4) {
    int t = blockIdx.x * blockDim.x + threadIdx.x;
    int stride = gridDim.x * blockDim.x;
    __half2* h2 = (__half2*)g_h;
    const int n4 = NN * DD / 4;
    for (int idx = t; idx < n4; idx += stride) {
        float4 v = x4[idx];
        h2[idx * 2 + 0] = __floats2half2_rn(v.x, v.y);
        h2[idx * 2 + 1] = __floats2half2_rn(v.z, v.w);
        out4[idx] = make_float4(0.25f * v.x, 0.25f * v.y, 0.25f * v.z, 0.25f * v.w);
    }
    for (int e = t; e < EE / 4; e += stride) {
        int4 d = dst4[e];
        atomicAdd(&g_deg[d.x], 1);
        atomicAdd(&g_deg[d.y], 1);
        atomicAdd(&g_deg[d.z], 1);
        atomicAdd(&g_deg[d.w], 1);
    }
}

// ----------------------------------------------------------------------------
// 2) single-pass scan with decoupled lookback (49 blocks, all resident).
// ----------------------------------------------------------------------------
__global__ void scan_kernel() {
    __shared__ int wsum[32];
    __shared__ int s_off;
    int b = blockIdx.x, tid = threadIdx.x;
    int i = b * TILE + tid;
    int lane = tid & 31, wid = tid >> 5;

    int v = (i < NN) ? g_deg[i] : 0;
    int s = v;
    #pragma unroll
    for (int off = 1; off < 32; off <<= 1) {
        int t = __shfl_up_sync(0xFFFFFFFF, s, off);
        if (lane >= off) s += t;
    }
    if (lane == 31) wsum[wid] = s;
    __syncthreads();
    if (wid == 0) {
        int ws = wsum[lane];
        #pragma unroll
        for (int off = 1; off < 32; off <<= 1) {
            int t = __shfl_up_sync(0xFFFFFFFF, ws, off);
            if (lane >= off) ws += t;
        }
        wsum[lane] = ws;
    }
    __syncthreads();
    int incl = s + (wid > 0 ? wsum[wid - 1] : 0);

    if (tid == 0) {
        g_bsum[b] = wsum[31];
        __threadfence();
        g_flag[b] = 1;
    }
    if (wid == 0) {
        int acc = 0;
        for (int j = lane; j < b; j += 32) {
            while (g_flag[j] == 0) { }   // all 49 blocks resident
            acc += g_bsum[j];
        }
        #pragma unroll
        for (int o = 16; o > 0; o >>= 1) acc += __shfl_down_sync(0xFFFFFFFF, acc, o);
        if (lane == 0) s_off = acc;
    }
    __syncthreads();
    int offset = s_off;

    if (i < NN) {
        int e = incl + offset;
        g_rowptr[i + 1] = e;
        g_cursor[i] = e - v;
    }
    if (b == 0 && tid == 0) g_rowptr[0] = 0;
}

// ----------------------------------------------------------------------------
// 3) scatter edges into CSR-by-dst (4 edges/thread, packed 8B stores).
//    Also re-zeroes g_deg / g_flag / g_ticket for the next replay.
// ----------------------------------------------------------------------------
__global__ void fill_kernel(const int4* __restrict__ src4,
                            const int4* __restrict__ dst4,
                            const float4* __restrict__ w4) {
    int t = blockIdx.x * blockDim.x + threadIdx.x;
    if (t < NN) g_deg[t] = 0;
    if (t < NBLK) g_flag[t] = 0;
    if (t < 4) g_ticket[t] = 0;
    if (t >= EE / 4) return;
    int4   s = src4[t];
    int4   d = dst4[t];
    float4 w = w4[t];
    int p0 = atomicAdd(&g_cursor[d.x], 1);
    int p1 = atomicAdd(&g_cursor[d.y], 1);
    int p2 = atomicAdd(&g_cursor[d.z], 1);
    int p3 = atomicAdd(&g_cursor[d.w], 1);
    g_csr[p0] = make_int2(s.x, __float_as_int(w.x));
    g_csr[p1] = make_int2(s.y, __float_as_int(w.y));
    g_csr[p2] = make_int2(s.z, __float_as_int(w.z));
    g_csr[p3] = make_int2(s.w, __float_as_int(w.w));
}

// ----------------------------------------------------------------------------
// 4) SpMM hop: persistent warps + ticket stealing; quarter-warp per dst row
//    (8 lanes x uint4 = one 128B fp16 row). Edge records for iteration i+1
//    are prefetched while iteration i's gathers are in flight.
// ----------------------------------------------------------------------------
__device__ __forceinline__ void acc8(float* a, float w, const uint4& p) {
    float2 f0 = __half22float2(*(const __half2*)&p.x);
    float2 f1 = __half22float2(*(const __half2*)&p.y);
    float2 f2 = __half22float2(*(const __half2*)&p.z);
    float2 f3 = __half22float2(*(const __half2*)&p.w);
    a[0] += w * f0.x; a[1] += w * f0.y;
    a[2] += w * f1.x; a[3] += w * f1.y;
    a[4] += w * f2.x; a[5] += w * f2.y;
    a[6] += w * f3.x; a[7] += w * f3.y;
}

template <bool LAST, int SLOT>
__global__ void __launch_bounds__(256, 5)
spmm_kernel(const __half* __restrict__ h,
            __half* __restrict__ hout,
            float* __restrict__ out) {
    const uint4* __restrict__ h8 = (const uint4*)h;   // 8 halves per uint4
    int lane  = threadIdx.x & 31;
    int q     = lane >> 3;
    int flane = lane & 7;

    for (;;) {
        int t;
        if (lane == 0) t = atomicAdd(&g_ticket[SLOT], 1);
        t = __shfl_sync(0xFFFFFFFF, t, 0);
        int base = t * 4;
        if (base >= NN) break;                 // warp-uniform exit
        int row = base + q;
        bool active = row < NN;

        int beg = 0, end = 0;
        if (active) { beg = g_rowptr[row]; end = g_rowptr[row + 1]; }

        float a[8] = {0.f, 0.f, 0.f, 0.f, 0.f, 0.f, 0.f, 0.f};

        int j = beg;
        int2 e0, e1, e2, e3;
        if (j + 3 < end) {
            e0 = __ldg(&g_csr[j]);     e1 = __ldg(&g_csr[j + 1]);
            e2 = __ldg(&g_csr[j + 2]); e3 = __ldg(&g_csr[j + 3]);
        }
        while (j + 3 < end) {
            uint4 p0 = __ldg(&h8[e0.x * 8 + flane]);
            uint4 p1 = __ldg(&h8[e1.x * 8 + flane]);
            uint4 p2 = __ldg(&h8[e2.x * 8 + flane]);
            uint4 p3 = __ldg(&h8[e3.x * 8 + flane]);
            int nj = j + 4;
            int2 f0, f1, f2, f3;                // prefetch next edge quad
            if (nj + 3 < end) {
                f0 = __ldg(&g_csr[nj]);     f1 = __ldg(&g_csr[nj + 1]);
                f2 = __ldg(&g_csr[nj + 2]); f3 = __ldg(&g_csr[nj + 3]);
            }
            acc8(a, __int_as_float(e0.y), p0);
            acc8(a, __int_as_float(e1.y), p1);
            acc8(a, __int_as_float(e2.y), p2);
            acc8(a, __int_as_float(e3.y), p3);
            e0 = f0; e1 = f1; e2 = f2; e3 = f3;
            j = nj;
        }
        for (; j < end; j++) {
            int2 e = __ldg(&g_csr[j]);
            uint4 p = __ldg(&h8[e.x * 8 + flane]);
            acc8(a, __int_as_float(e.y), p);
        }

        if (active) {
            if (!LAST) {
                uint4 packed;
                *(__half2*)&packed.x = __floats2half2_rn(a[0], a[1]);
                *(__half2*)&packed.y = __floats2half2_rn(a[2], a[3]);
                *(__half2*)&packed.z = __floats2half2_rn(a[4], a[5]);
                *(__half2*)&packed.w = __floats2half2_rn(a[6], a[7]);
                ((uint4*)hout)[row * 8 + flane] = packed;
            }
            float4* o = (float4*)out + row * 16 + flane * 2;
            float4 o0 = o[0], o1 = o[1];
            o0.x += 0.25f * a[0]; o0.y += 0.25f * a[1];
            o0.z += 0.25f * a[2]; o0.w += 0.25f * a[3];
            o1.x += 0.25f * a[4]; o1.y += 0.25f * a[5];
            o1.z += 0.25f * a[6]; o1.w += 0.25f * a[7];
            o[0] = o0; o[1] = o1;
        }
    }
}

// ----------------------------------------------------------------------------
// launch (6 kernels total)
// ----------------------------------------------------------------------------
extern "C" void kernel_launch(void* const* d_in, const int* in_sizes, int n_in,
                              void* d_out, int out_size) {
    const float* x   = (const float*)d_in[0];
    const float* w   = (const float*)d_in[1];
    const int*   src = (const int*)d_in[2];
    const int*   dst = (const int*)d_in[3];
    float*       out = (float*)d_out;

    (void)in_sizes; (void)n_in; (void)out_size;

    __half* hA; __half* hB;
    cudaGetSymbolAddress((void**)&hA, g_h);
    cudaGetSymbolAddress((void**)&hB, g_t);

    // 1) init + histogram
    init_count_kernel<<<1024, 256>>>((const float4*)x, (float4*)out, (const int4*)dst);
    // 2) one-pass scan -> rowptr + cursor
    scan_kernel<<<NBLK, TILE>>>();
    // 3) CSR scatter (also resets g_deg / g_flag / g_ticket for the next replay)
    fill_kernel<<<(EE / 4 + 255) / 256, 256>>>((const int4*)src, (const int4*)dst,
                                               (const float4*)w);

    // 4-6) K=3 hops, persistent ticket-stealing warps, ping-pong fp16 buffers,
    //      fused residual (+0.25*h) into out
    dim3 blk(256);
    dim3 grd(148 * 5);                         // 5 blocks/SM residency target
    spmm_kernel<false, 0><<<grd, blk>>>(hA, hB, out);   // hop 1: x    -> g_t
    spmm_kernel<false, 1><<<grd, blk>>>(hB, hA, out);   // hop 2: g_t  -> g_h
    spmm_kernel<true,  2><<<grd, blk>>>(hA, hB, out);   // hop 3: residual only
}

// round 9
// speedup vs baseline: 1.1247x; 1.1247x over previous
#include <cuda_runtime.h>
#include <cuda_fp16.h>
#include <cstdint>

// Problem constants (match reference_code)
#define NN 50000
#define EE 800000
#define DD 64

#define TILE 1024
#define NBLK ((NN + TILE - 1) / TILE)   // 49

// ----------------------------------------------------------------------------
// Scratch (device globals; no allocation allowed). BSS-zeroed at load;
// fill_kernel re-zeroes g_deg / g_flag each call, so every graph replay sees
// identical initial state.
// ----------------------------------------------------------------------------
__device__ __half g_h[NN * DD];       // ping (fp16 inter-hop tensor)
__device__ __half g_t[NN * DD];       // pong
__device__ int    g_deg[NN];          // in-degree histogram (zero at entry)
__device__ int    g_rowptr[NN + 1];   // CSR row pointers (by dst)
__device__ int    g_cursor[NN];       // scatter cursors
__device__ volatile int g_bsum[NBLK]; // scan block sums
__device__ volatile int g_flag[NBLK]; // scan lookback flags (zero at entry)
__device__ int2   g_csr[EE];          // packed {src, w_bits} per CSR slot

// ----------------------------------------------------------------------------
// 1) init + count fused: g_h = fp16(x); out = 0.25*x; histogram of dst.
// ----------------------------------------------------------------------------
__global__ void init_count_kernel(const float4* __restrict__ x4,
                                  float4* __restrict__ out4,
                                  const int4* __restrict__ dst4) {
    int t = blockIdx.x * blockDim.x + threadIdx.x;
    int stride = gridDim.x * blockDim.x;
    __half2* h2 = (__half2*)g_h;
    const int n4 = NN * DD / 4;
    for (int idx = t; idx < n4; idx += stride) {
        float4 v = x4[idx];
        h2[idx * 2 + 0] = __floats2half2_rn(v.x, v.y);
        h2[idx * 2 + 1] = __floats2half2_rn(v.z, v.w);
        out4[idx] = make_float4(0.25f * v.x, 0.25f * v.y, 0.25f * v.z, 0.25f * v.w);
    }
    for (int e = t; e < EE / 4; e += stride) {
        int4 d = dst4[e];
        atomicAdd(&g_deg[d.x], 1);
        atomicAdd(&g_deg[d.y], 1);
        atomicAdd(&g_deg[d.z], 1);
        atomicAdd(&g_deg[d.w], 1);
    }
}

// ----------------------------------------------------------------------------
// 2) single-pass scan with decoupled lookback (49 blocks, all resident).
// ----------------------------------------------------------------------------
__global__ void scan_kernel() {
    __shared__ int wsum[32];
    __shared__ int s_off;
    int b = blockIdx.x, tid = threadIdx.x;
    int i = b * TILE + tid;
    int lane = tid & 31, wid = tid >> 5;

    int v = (i < NN) ? g_deg[i] : 0;
    int s = v;
    #pragma unroll
    for (int off = 1; off < 32; off <<= 1) {
        int t = __shfl_up_sync(0xFFFFFFFF, s, off);
        if (lane >= off) s += t;
    }
    if (lane == 31) wsum[wid] = s;
    __syncthreads();
    if (wid == 0) {
        int ws = wsum[lane];
        #pragma unroll
        for (int off = 1; off < 32; off <<= 1) {
            int t = __shfl_up_sync(0xFFFFFFFF, ws, off);
            if (lane >= off) ws += t;
        }
        wsum[lane] = ws;
    }
    __syncthreads();
    int incl = s + (wid > 0 ? wsum[wid - 1] : 0);

    if (tid == 0) {
        g_bsum[b] = wsum[31];
        __threadfence();
        g_flag[b] = 1;
    }
    if (wid == 0) {
        int acc = 0;
        for (int j = lane; j < b; j += 32) {
            while (g_flag[j] == 0) { }   // all 49 blocks resident
            acc += g_bsum[j];
        }
        #pragma unroll
        for (int o = 16; o > 0; o >>= 1) acc += __shfl_down_sync(0xFFFFFFFF, acc, o);
        if (lane == 0) s_off = acc;
    }
    __syncthreads();
    int offset = s_off;

    if (i < NN) {
        int e = incl + offset;
        g_rowptr[i + 1] = e;
        g_cursor[i] = e - v;
    }
    if (b == 0 && tid == 0) g_rowptr[0] = 0;
}

// ----------------------------------------------------------------------------
// 3) scatter edges into CSR-by-dst (4 edges/thread, packed 8B stores).
//    Also re-zeroes g_deg / g_flag for the next replay.
// ----------------------------------------------------------------------------
__global__ void fill_kernel(const int4* __restrict__ src4,
                            const int4* __restrict__ dst4,
                            const float4* __restrict__ w4) {
    int t = blockIdx.x * blockDim.x + threadIdx.x;
    if (t < NN) g_deg[t] = 0;
    if (t < NBLK) g_flag[t] = 0;
    if (t >= EE / 4) return;
    int4   s = src4[t];
    int4   d = dst4[t];
    float4 w = w4[t];
    int p0 = atomicAdd(&g_cursor[d.x], 1);
    int p1 = atomicAdd(&g_cursor[d.y], 1);
    int p2 = atomicAdd(&g_cursor[d.z], 1);
    int p3 = atomicAdd(&g_cursor[d.w], 1);
    g_csr[p0] = make_int2(s.x, __float_as_int(w.x));
    g_csr[p1] = make_int2(s.y, __float_as_int(w.y));
    g_csr[p2] = make_int2(s.z, __float_as_int(w.z));
    g_csr[p3] = make_int2(s.w, __float_as_int(w.w));
}

// ----------------------------------------------------------------------------
// 4) SpMM hop: HALF-warp per dst row, 4 features per lane (16 lanes x uint2
//    = one 128B fp16 row per gather). Two rows progress per warp-iteration;
//    each warp covers 4 rows total (2 sequential x 2 concurrent halves).
//    ~5-6 warp-inst per edge. fp32 accumulation.
// ----------------------------------------------------------------------------
__device__ __forceinline__ void acc4(float* a, float w, const uint2& p) {
    float2 f0 = __half22float2(*(const __half2*)&p.x);
    float2 f1 = __half22float2(*(const __half2*)&p.y);
    a[0] += w * f0.x; a[1] += w * f0.y;
    a[2] += w * f1.x; a[3] += w * f1.y;
}

template <bool LAST>
__global__ void __launch_bounds__(256, 5)
spmm_kernel(const __half* __restrict__ h,
            __half* __restrict__ hout,
            float* __restrict__ out) {
    const uint2* __restrict__ h4 = (const uint2*)h;   // 4 halves per uint2; 16 per row
    int wid   = threadIdx.x >> 5;
    int warp  = blockIdx.x * (blockDim.x >> 5) + wid;
    int lane  = threadIdx.x & 31;
    int half  = lane >> 4;        // which half-warp
    int hlane = lane & 15;        // lane within half: owns features hlane*4..+3

    int base = warp * 4;          // 4 rows per warp: 2 iterations x 2 halves

    #pragma unroll
    for (int r = 0; r < 2; r++) {
        int row = base + r * 2 + half;
        if (row >= NN) continue;

        int beg = g_rowptr[row];
        int end = g_rowptr[row + 1];

        float a[4] = {0.f, 0.f, 0.f, 0.f};

        int j = beg;
        for (; j + 3 < end; j += 4) {
            int2 e0 = __ldg(&g_csr[j]);
            int2 e1 = __ldg(&g_csr[j + 1]);
            int2 e2 = __ldg(&g_csr[j + 2]);
            int2 e3 = __ldg(&g_csr[j + 3]);
            uint2 p0 = __ldg(&h4[e0.x * 16 + hlane]);
            uint2 p1 = __ldg(&h4[e1.x * 16 + hlane]);
            uint2 p2 = __ldg(&h4[e2.x * 16 + hlane]);
            uint2 p3 = __ldg(&h4[e3.x * 16 + hlane]);
            acc4(a, __int_as_float(e0.y), p0);
            acc4(a, __int_as_float(e1.y), p1);
            acc4(a, __int_as_float(e2.y), p2);
            acc4(a, __int_as_float(e3.y), p3);
        }
        for (; j < end; j++) {
            int2 e = __ldg(&g_csr[j]);
            uint2 p = __ldg(&h4[e.x * 16 + hlane]);
            acc4(a, __int_as_float(e.y), p);
        }

        if (!LAST) {
            uint2 packed;
            *(__half2*)&packed.x = __floats2half2_rn(a[0], a[1]);
            *(__half2*)&packed.y = __floats2half2_rn(a[2], a[3]);
            ((uint2*)hout)[row * 16 + hlane] = packed;
        }

        // out RMW: lane owns floats [row*64 + hlane*4, +4) -> one float4
        float4* o = (float4*)out + row * 16 + hlane;
        float4 ov = *o;
        ov.x += 0.25f * a[0];
        ov.y += 0.25f * a[1];
        ov.z += 0.25f * a[2];
        ov.w += 0.25f * a[3];
        *o = ov;
    }
}

// ----------------------------------------------------------------------------
// launch (6 kernels total)
// ----------------------------------------------------------------------------
extern "C" void kernel_launch(void* const* d_in, const int* in_sizes, int n_in,
                              void* d_out, int out_size) {
    const float* x   = (const float*)d_in[0];
    const float* w   = (const float*)d_in[1];
    const int*   src = (const int*)d_in[2];
    const int*   dst = (const int*)d_in[3];
    float*       out = (float*)d_out;

    (void)in_sizes; (void)n_in; (void)out_size;

    __half* hA; __half* hB;
    cudaGetSymbolAddress((void**)&hA, g_h);
    cudaGetSymbolAddress((void**)&hB, g_t);

    // 1) init + histogram
    init_count_kernel<<<1024, 256>>>((const float4*)x, (float4*)out, (const int4*)dst);
    // 2) one-pass scan -> rowptr + cursor
    scan_kernel<<<NBLK, TILE>>>();
    // 3) CSR scatter (also resets g_deg / g_flag for the next replay)
    fill_kernel<<<(EE / 4 + 255) / 256, 256>>>((const int4*)src, (const int4*)dst,
                                               (const float4*)w);

    // 4-6) K=3 hops, 4 rows per warp (2 concurrent half-warp rows x 2),
    //      ping-pong fp16 buffers, fused residual (+0.25*h) into out
    const int WPB = 8;                            // 8 warps = 32 rows per block
    dim3 blk(WPB * 32);
    dim3 grd((NN + WPB * 4 - 1) / (WPB * 4));     // 1563 blocks
    spmm_kernel<false><<<grd, blk>>>(hA, hB, out);   // hop 1: x    -> g_t
    spmm_kernel<false><<<grd, blk>>>(hB, hA, out);   // hop 2: g_t  -> g_h
    spmm_kernel<true ><<<grd, blk>>>(hA, hB, out);   // hop 3: residual only
}

// round 10
// speedup vs baseline: 1.1274x; 1.0024x over previous
#include <cuda_runtime.h>
#include <cuda_fp16.h>
#include <cstdint>

// Problem constants (match reference_code)
#define NN 50000
#define EE 800000
#define DD 64

#define TILE 1024
#define NBLK ((NN + TILE - 1) / TILE)   // 49
#define NCHUNK (NN / 4)                 // 12500 (NN % 4 == 0)

// ----------------------------------------------------------------------------
// Scratch (device globals; no allocation allowed). BSS-zeroed at load;
// fill_kernel re-zeroes g_deg / g_flag / g_bins each call, so every graph
// replay sees identical initial state.
// ----------------------------------------------------------------------------
__device__ __half g_h[NN * DD];       // ping (fp16 inter-hop tensor)
__device__ __half g_t[NN * DD];       // pong
__device__ int    g_deg[NN];          // in-degree histogram (zero at entry)
__device__ int    g_rowptr[NN + 1];   // CSR row pointers (by dst)
__device__ int    g_cursor[NN];       // scatter cursors
__device__ volatile int g_bsum[NBLK]; // scan block sums
__device__ volatile int g_flag[NBLK]; // scan lookback flags (zero at entry)
__device__ int    g_bins[256];        // degree histogram bins (zero at entry)
__device__ int    g_bcur[256];        // bin cursors (descending-degree starts)
__device__ int    g_perm[NN];         // rows sorted by descending degree
__device__ int2   g_csr[EE];          // packed {src, w_bits} per CSR slot

// ----------------------------------------------------------------------------
// 1) init + count fused: g_h = fp16(x); out = 0.25*x; histogram of dst.
// ----------------------------------------------------------------------------
__global__ void init_count_kernel(const float4* __restrict__ x4,
                                  float4* __restrict__ out4,
                                  const int4* __restrict__ dst4) {
    int t = blockIdx.x * blockDim.x + threadIdx.x;
    int stride = gridDim.x * blockDim.x;
    __half2* h2 = (__half2*)g_h;
    const int n4 = NN * DD / 4;
    for (int idx = t; idx < n4; idx += stride) {
        float4 v = x4[idx];
        h2[idx * 2 + 0] = __floats2half2_rn(v.x, v.y);
        h2[idx * 2 + 1] = __floats2half2_rn(v.z, v.w);
        out4[idx] = make_float4(0.25f * v.x, 0.25f * v.y, 0.25f * v.z, 0.25f * v.w);
    }
    for (int e = t; e < EE / 4; e += stride) {
        int4 d = dst4[e];
        atomicAdd(&g_deg[d.x], 1);
        atomicAdd(&g_deg[d.y], 1);
        atomicAdd(&g_deg[d.z], 1);
        atomicAdd(&g_deg[d.w], 1);
    }
}

// ----------------------------------------------------------------------------
// 2) single-pass scan with decoupled lookback (49 blocks, all resident).
//    Also builds a 256-bin degree histogram (smem-staged) for counting sort.
// ----------------------------------------------------------------------------
__global__ void scan_kernel() {
    __shared__ int wsum[32];
    __shared__ int s_off;
    __shared__ int s_bins[256];
    int b = blockIdx.x, tid = threadIdx.x;
    int i = b * TILE + tid;
    int lane = tid & 31, wid = tid >> 5;

    if (tid < 256) s_bins[tid] = 0;
    __syncthreads();

    int v = (i < NN) ? g_deg[i] : 0;
    if (i < NN) atomicAdd(&s_bins[v > 255 ? 255 : v], 1);

    int s = v;
    #pragma unroll
    for (int off = 1; off < 32; off <<= 1) {
        int t = __shfl_up_sync(0xFFFFFFFF, s, off);
        if (lane >= off) s += t;
    }
    if (lane == 31) wsum[wid] = s;
    __syncthreads();
    if (wid == 0) {
        int ws = wsum[lane];
        #pragma unroll
        for (int off = 1; off < 32; off <<= 1) {
            int t = __shfl_up_sync(0xFFFFFFFF, ws, off);
            if (lane >= off) ws += t;
        }
        wsum[lane] = ws;
    }
    __syncthreads();
    int incl = s + (wid > 0 ? wsum[wid - 1] : 0);

    if (tid == 0) {
        g_bsum[b] = wsum[31];
        __threadfence();
        g_flag[b] = 1;
    }
    if (wid == 0) {
        int acc = 0;
        for (int j = lane; j < b; j += 32) {
            while (g_flag[j] == 0) { }   // all 49 blocks resident
            acc += g_bsum[j];
        }
        #pragma unroll
        for (int o = 16; o > 0; o >>= 1) acc += __shfl_down_sync(0xFFFFFFFF, acc, o);
        if (lane == 0) s_off = acc;
    }
    __syncthreads();
    int offset = s_off;

    if (i < NN) {
        int e = incl + offset;
        g_rowptr[i + 1] = e;
        g_cursor[i] = e - v;
    }
    if (b == 0 && tid == 0) g_rowptr[0] = 0;

    if (tid < 256) atomicAdd(&g_bins[tid], s_bins[tid]);
}

// ----------------------------------------------------------------------------
// 2b) suffix-scan the 256 degree bins -> descending-degree bin start offsets.
//     g_bcur[d] = number of rows with degree > d.
// ----------------------------------------------------------------------------
__global__ void bin_scan_kernel() {
    __shared__ int sm[256];
    int tid = threadIdx.x;          // 256 threads
    int r = 255 - tid;              // reversed index
    int cnt = g_bins[r];
    sm[tid] = cnt;
    __syncthreads();
    #pragma unroll
    for (int off = 1; off < 256; off <<= 1) {
        int t = (tid >= off) ? sm[tid - off] : 0;
        __syncthreads();
        sm[tid] += t;
        __syncthreads();
    }
    g_bcur[r] = sm[tid] - cnt;      // exclusive suffix sum (descending start)
}

// ----------------------------------------------------------------------------
// 3) scatter edges into CSR-by-dst (4 edges/thread, packed 8B stores).
//    Also: counting-sort scatter of rows by descending degree into g_perm,
//    and reset of g_deg / g_bins / g_flag for the next replay.
// ----------------------------------------------------------------------------
__global__ void fill_kernel(const int4* __restrict__ src4,
                            const int4* __restrict__ dst4,
                            const float4* __restrict__ w4) {
    int t = blockIdx.x * blockDim.x + threadIdx.x;
    if (t < NN) {
        int d = g_deg[t];
        int p = atomicAdd(&g_bcur[d > 255 ? 255 : d], 1);
        g_perm[p] = t;
        g_deg[t] = 0;
    }
    if (t < 256) g_bins[t] = 0;
    if (t < NBLK) g_flag[t] = 0;
    if (t >= EE / 4) return;
    int4   s = src4[t];
    int4   d = dst4[t];
    float4 w = w4[t];
    int p0 = atomicAdd(&g_cursor[d.x], 1);
    int p1 = atomicAdd(&g_cursor[d.y], 1);
    int p2 = atomicAdd(&g_cursor[d.z], 1);
    int p3 = atomicAdd(&g_cursor[d.w], 1);
    g_csr[p0] = make_int2(s.x, __float_as_int(w.x));
    g_csr[p1] = make_int2(s.y, __float_as_int(w.y));
    g_csr[p2] = make_int2(s.z, __float_as_int(w.z));
    g_csr[p3] = make_int2(s.w, __float_as_int(w.w));
}

// ----------------------------------------------------------------------------
// 4) SpMM hop: quarter-warp per dst row (8 lanes x uint4 = one 128B fp16 row),
//    rows taken from g_perm (descending degree) so the 4 quarters of a warp
//    handle near-equal degrees (minimal divergence). Persistent grid with a
//    static chunk-stride loop: longest rows scheduled first, no wave tail,
//    no scheduling atomics. fp32 accumulation.
// ----------------------------------------------------------------------------
__device__ __forceinline__ void acc8(float* a, float w, const uint4& p) {
    float2 f0 = __half22float2(*(const __half2*)&p.x);
    float2 f1 = __half22float2(*(const __half2*)&p.y);
    float2 f2 = __half22float2(*(const __half2*)&p.z);
    float2 f3 = __half22float2(*(const __half2*)&p.w);
    a[0] += w * f0.x; a[1] += w * f0.y;
    a[2] += w * f1.x; a[3] += w * f1.y;
    a[4] += w * f2.x; a[5] += w * f2.y;
    a[6] += w * f3.x; a[7] += w * f3.y;
}

template <bool LAST>
__global__ void __launch_bounds__(256, 5)
spmm_kernel(const __half* __restrict__ h,
            __half* __restrict__ hout,
            float* __restrict__ out) {
    const uint4* __restrict__ h8 = (const uint4*)h;   // 8 halves per uint4
    int wid   = threadIdx.x >> 5;
    int warp  = blockIdx.x * (blockDim.x >> 5) + wid;
    int nwarp = gridDim.x * (blockDim.x >> 5);
    int lane  = threadIdx.x & 31;
    int q     = lane >> 3;
    int flane = lane & 7;

    for (int c = warp; c < NCHUNK; c += nwarp) {
        int row = g_perm[c * 4 + q];            // NN % 4 == 0: always valid

        int beg = g_rowptr[row];
        int end = g_rowptr[row + 1];

        float a[8] = {0.f, 0.f, 0.f, 0.f, 0.f, 0.f, 0.f, 0.f};

        int j = beg;
        for (; j + 3 < end; j += 4) {
            int2 e0 = __ldg(&g_csr[j]);
            int2 e1 = __ldg(&g_csr[j + 1]);
            int2 e2 = __ldg(&g_csr[j + 2]);
            int2 e3 = __ldg(&g_csr[j + 3]);
            uint4 p0 = __ldg(&h8[e0.x * 8 + flane]);
            uint4 p1 = __ldg(&h8[e1.x * 8 + flane]);
            uint4 p2 = __ldg(&h8[e2.x * 8 + flane]);
            uint4 p3 = __ldg(&h8[e3.x * 8 + flane]);
            acc8(a, __int_as_float(e0.y), p0);
            acc8(a, __int_as_float(e1.y), p1);
            acc8(a, __int_as_float(e2.y), p2);
            acc8(a, __int_as_float(e3.y), p3);
        }
        for (; j < end; j++) {
            int2 e = __ldg(&g_csr[j]);
            uint4 p = __ldg(&h8[e.x * 8 + flane]);
            acc8(a, __int_as_float(e.y), p);
        }

        if (!LAST) {
            uint4 packed;
            *(__half2*)&packed.x = __floats2half2_rn(a[0], a[1]);
            *(__half2*)&packed.y = __floats2half2_rn(a[2], a[3]);
            *(__half2*)&packed.z = __floats2half2_rn(a[4], a[5]);
            *(__half2*)&packed.w = __floats2half2_rn(a[6], a[7]);
            ((uint4*)hout)[row * 8 + flane] = packed;
        }

        float4* o = (float4*)out + row * 16 + flane * 2;
        float4 o0 = o[0], o1 = o[1];
        o0.x += 0.25f * a[0]; o0.y += 0.25f * a[1];
        o0.z += 0.25f * a[2]; o0.w += 0.25f * a[3];
        o1.x += 0.25f * a[4]; o1.y += 0.25f * a[5];
        o1.z += 0.25f * a[6]; o1.w += 0.25f * a[7];
        o[0] = o0; o[1] = o1;
    }
}

// ----------------------------------------------------------------------------
// launch (7 kernels total)
// ----------------------------------------------------------------------------
extern "C" void kernel_launch(void* const* d_in, const int* in_sizes, int n_in,
                              void* d_out, int out_size) {
    const float* x   = (const float*)d_in[0];
    const float* w   = (const float*)d_in[1];
    const int*   src = (const int*)d_in[2];
    const int*   dst = (const int*)d_in[3];
    float*       out = (float*)d_out;

    (void)in_sizes; (void)n_in; (void)out_size;

    __half* hA; __half* hB;
    cudaGetSymbolAddress((void**)&hA, g_h);
    cudaGetSymbolAddress((void**)&hB, g_t);

    // 1) init + histogram
    init_count_kernel<<<1024, 256>>>((const float4*)x, (float4*)out, (const int4*)dst);
    // 2) one-pass scan -> rowptr + cursor (+ degree bins)
    scan_kernel<<<NBLK, TILE>>>();
    // 2b) bin suffix-scan -> descending-degree bin starts
    bin_scan_kernel<<<1, 256>>>();
    // 3) CSR scatter + counting-sort rows into g_perm (+ state resets)
    fill_kernel<<<(EE / 4 + 255) / 256, 256>>>((const int4*)src, (const int4*)dst,
                                               (const float4*)w);

    // 4-6) K=3 hops, persistent grid, degree-balanced quarter-warp rows,
    //      ping-pong fp16 buffers, fused residual (+0.25*h) into out
    dim3 blk(256);
    dim3 grd(148 * 5);                               // persistent: 5 blocks/SM
    spmm_kernel<false><<<grd, blk>>>(hA, hB, out);   // hop 1: x    -> g_t
    spmm_kernel<false><<<grd, blk>>>(hB, hA, out);   // hop 2: g_t  -> g_h
    spmm_kernel<true ><<<grd, blk>>>(hA, hB, out);   // hop 3: residual only
}

// round 11
// speedup vs baseline: 1.2175x; 1.0800x over previous
#include <cuda_runtime.h>
#include <cuda_fp16.h>
#include <cstdint>

// Problem constants (match reference_code)
#define NN 50000
#define EE 800000
#define DD 64

#define TILE 1024
#define NBLK ((NN + TILE - 1) / TILE)   // 49
#define NCHUNK ((NN + 3) / 4)           // 12500 row-quads

// ----------------------------------------------------------------------------
// Scratch (device globals; no allocation allowed). BSS-zeroed at load;
// fill_kernel re-zeroes g_deg / g_flag each call, so every graph replay sees
// identical initial state.
// ----------------------------------------------------------------------------
__device__ __half g_h[NN * DD];       // ping (fp16 inter-hop tensor)
__device__ __half g_t[NN * DD];       // pong
__device__ int    g_deg[NN];          // in-degree histogram (zero at entry)
__device__ int    g_rowptr[NN + 1];   // CSR row pointers (by dst)
__device__ int    g_cursor[NN];       // scatter cursors
__device__ volatile int g_bsum[NBLK]; // scan block sums
__device__ volatile int g_flag[NBLK]; // scan lookback flags (zero at entry)
__device__ int2   g_csr[EE];          // packed {src, w_bits} per CSR slot

// ----------------------------------------------------------------------------
// 1) init + count fused: g_h = fp16(x); out = 0.25*x; histogram of dst.
// ----------------------------------------------------------------------------
__global__ void init_count_kernel(const float4* __restrict__ x4,
                                  float4* __restrict__ out4,
                                  const int4* __restrict__ dst4) {
    int t = blockIdx.x * blockDim.x + threadIdx.x;
    int stride = gridDim.x * blockDim.x;
    __half2* h2 = (__half2*)g_h;
    const int n4 = NN * DD / 4;
    for (int idx = t; idx < n4; idx += stride) {
        float4 v = x4[idx];
        h2[idx * 2 + 0] = __floats2half2_rn(v.x, v.y);
        h2[idx * 2 + 1] = __floats2half2_rn(v.z, v.w);
        out4[idx] = make_float4(0.25f * v.x, 0.25f * v.y, 0.25f * v.z, 0.25f * v.w);
    }
    for (int e = t; e < EE / 4; e += stride) {
        int4 d = dst4[e];
        atomicAdd(&g_deg[d.x], 1);
        atomicAdd(&g_deg[d.y], 1);
        atomicAdd(&g_deg[d.z], 1);
        atomicAdd(&g_deg[d.w], 1);
    }
}

// ----------------------------------------------------------------------------
// 2) single-pass scan with decoupled lookback (49 blocks, all resident).
// ----------------------------------------------------------------------------
__global__ void scan_kernel() {
    __shared__ int wsum[32];
    __shared__ int s_off;
    int b = blockIdx.x, tid = threadIdx.x;
    int i = b * TILE + tid;
    int lane = tid & 31, wid = tid >> 5;

    int v = (i < NN) ? g_deg[i] : 0;
    int s = v;
    #pragma unroll
    for (int off = 1; off < 32; off <<= 1) {
        int t = __shfl_up_sync(0xFFFFFFFF, s, off);
        if (lane >= off) s += t;
    }
    if (lane == 31) wsum[wid] = s;
    __syncthreads();
    if (wid == 0) {
        int ws = wsum[lane];
        #pragma unroll
        for (int off = 1; off < 32; off <<= 1) {
            int t = __shfl_up_sync(0xFFFFFFFF, ws, off);
            if (lane >= off) ws += t;
        }
        wsum[lane] = ws;
    }
    __syncthreads();
    int incl = s + (wid > 0 ? wsum[wid - 1] : 0);

    if (tid == 0) {
        g_bsum[b] = wsum[31];
        __threadfence();
        g_flag[b] = 1;
    }
    if (wid == 0) {
        int acc = 0;
        for (int j = lane; j < b; j += 32) {
            while (g_flag[j] == 0) { }   // all 49 blocks resident
            acc += g_bsum[j];
        }
        #pragma unroll
        for (int o = 16; o > 0; o >>= 1) acc += __shfl_down_sync(0xFFFFFFFF, acc, o);
        if (lane == 0) s_off = acc;
    }
    __syncthreads();
    int offset = s_off;

    if (i < NN) {
        int e = incl + offset;
        g_rowptr[i + 1] = e;
        g_cursor[i] = e - v;
    }
    if (b == 0 && tid == 0) g_rowptr[0] = 0;
}

// ----------------------------------------------------------------------------
// 3) scatter edges into CSR-by-dst (4 edges/thread, packed 8B stores).
//    Also re-zeroes g_deg / g_flag for the next replay.
// ----------------------------------------------------------------------------
__global__ void fill_kernel(const int4* __restrict__ src4,
                            const int4* __restrict__ dst4,
                            const float4* __restrict__ w4) {
    int t = blockIdx.x * blockDim.x + threadIdx.x;
    if (t < NN) g_deg[t] = 0;
    if (t < NBLK) g_flag[t] = 0;
    if (t >= EE / 4) return;
    int4   s = src4[t];
    int4   d = dst4[t];
    float4 w = w4[t];
    int p0 = atomicAdd(&g_cursor[d.x], 1);
    int p1 = atomicAdd(&g_cursor[d.y], 1);
    int p2 = atomicAdd(&g_cursor[d.z], 1);
    int p3 = atomicAdd(&g_cursor[d.w], 1);
    g_csr[p0] = make_int2(s.x, __float_as_int(w.x));
    g_csr[p1] = make_int2(s.y, __float_as_int(w.y));
    g_csr[p2] = make_int2(s.z, __float_as_int(w.z));
    g_csr[p3] = make_int2(s.w, __float_as_int(w.w));
}

// ----------------------------------------------------------------------------
// 4) SpMM hop: quarter-warp per dst row (8 lanes x uint4 = one 128B fp16 row).
//    Persistent grid, static chunk-stride loop (no scheduling atomics), 6
//    blocks/SM for latency coverage. fp32 accumulation.
// ----------------------------------------------------------------------------
__device__ __forceinline__ void acc8(float* a, float w, const uint4& p) {
    float2 f0 = __half22float2(*(const __half2*)&p.x);
    float2 f1 = __half22float2(*(const __half2*)&p.y);
    float2 f2 = __half22float2(*(const __half2*)&p.z);
    float2 f3 = __half22float2(*(const __half2*)&p.w);
    a[0] += w * f0.x; a[1] += w * f0.y;
    a[2] += w * f1.x; a[3] += w * f1.y;
    a[4] += w * f2.x; a[5] += w * f2.y;
    a[6] += w * f3.x; a[7] += w * f3.y;
}

template <bool LAST>
__global__ void __launch_bounds__(256, 6)
spmm_kernel(const __half* __restrict__ h,
            __half* __restrict__ hout,
            float* __restrict__ out) {
    const uint4* __restrict__ h8 = (const uint4*)h;   // 8 halves per uint4
    int wid   = threadIdx.x >> 5;
    int warp  = blockIdx.x * (blockDim.x >> 5) + wid;
    int nwarp = gridDim.x * (blockDim.x >> 5);
    int lane  = threadIdx.x & 31;
    int q     = lane >> 3;
    int flane = lane & 7;

    for (int c = warp; c < NCHUNK; c += nwarp) {
        int row = c * 4 + q;                    // NN % 4 == 0: always < NN

        int beg = g_rowptr[row];
        int end = g_rowptr[row + 1];

        float a[8] = {0.f, 0.f, 0.f, 0.f, 0.f, 0.f, 0.f, 0.f};

        int j = beg;
        for (; j + 3 < end; j += 4) {
            int2 e0 = __ldg(&g_csr[j]);
            int2 e1 = __ldg(&g_csr[j + 1]);
            int2 e2 = __ldg(&g_csr[j + 2]);
            int2 e3 = __ldg(&g_csr[j + 3]);
            uint4 p0 = __ldg(&h8[e0.x * 8 + flane]);
            uint4 p1 = __ldg(&h8[e1.x * 8 + flane]);
            uint4 p2 = __ldg(&h8[e2.x * 8 + flane]);
            uint4 p3 = __ldg(&h8[e3.x * 8 + flane]);
            acc8(a, __int_as_float(e0.y), p0);
            acc8(a, __int_as_float(e1.y), p1);
            acc8(a, __int_as_float(e2.y), p2);
            acc8(a, __int_as_float(e3.y), p3);
        }
        for (; j < end; j++) {
            int2 e = __ldg(&g_csr[j]);
            uint4 p = __ldg(&h8[e.x * 8 + flane]);
            acc8(a, __int_as_float(e.y), p);
        }

        if (!LAST) {
            uint4 packed;
            *(__half2*)&packed.x = __floats2half2_rn(a[0], a[1]);
            *(__half2*)&packed.y = __floats2half2_rn(a[2], a[3]);
            *(__half2*)&packed.z = __floats2half2_rn(a[4], a[5]);
            *(__half2*)&packed.w = __floats2half2_rn(a[6], a[7]);
            ((uint4*)hout)[row * 8 + flane] = packed;
        }

        float4* o = (float4*)out + row * 16 + flane * 2;
        float4 o0 = o[0], o1 = o[1];
        o0.x += 0.25f * a[0]; o0.y += 0.25f * a[1];
        o0.z += 0.25f * a[2]; o0.w += 0.25f * a[3];
        o1.x += 0.25f * a[4]; o1.y += 0.25f * a[5];
        o1.z += 0.25f * a[6]; o1.w += 0.25f * a[7];
        o[0] = o0; o[1] = o1;
    }
}

// ----------------------------------------------------------------------------
// launch (6 kernels total)
// ----------------------------------------------------------------------------
extern "C" void kernel_launch(void* const* d_in, const int* in_sizes, int n_in,
                              void* d_out, int out_size) {
    const float* x   = (const float*)d_in[0];
    const float* w   = (const float*)d_in[1];
    const int*   src = (const int*)d_in[2];
    const int*   dst = (const int*)d_in[3];
    float*       out = (float*)d_out;

    (void)in_sizes; (void)n_in; (void)out_size;

    __half* hA; __half* hB;
    cudaGetSymbolAddress((void**)&hA, g_h);
    cudaGetSymbolAddress((void**)&hB, g_t);

    // 1) init + histogram
    init_count_kernel<<<1024, 256>>>((const float4*)x, (float4*)out, (const int4*)dst);
    // 2) one-pass scan -> rowptr + cursor
    scan_kernel<<<NBLK, TILE>>>();
    // 3) CSR scatter (also resets g_deg / g_flag for the next replay)
    fill_kernel<<<(EE / 4 + 255) / 256, 256>>>((const int4*)src, (const int4*)dst,
                                               (const float4*)w);

    // 4-6) K=3 hops, persistent grid (6 blocks/SM), quarter-warp rows,
    //      ping-pong fp16 buffers, fused residual (+0.25*h) into out
    dim3 blk(256);
    dim3 grd(148 * 6);                               // persistent: 6 blocks/SM
    spmm_kernel<false><<<grd, blk>>>(hA, hB, out);   // hop 1: x    -> g_t
    spmm_kernel<false><<<grd, blk>>>(hB, hA, out);   // hop 2: g_t  -> g_h
    spmm_kernel<true ><<<grd, blk>>>(hA, hB, out);   // hop 3: residual only
}